// round 10
// baseline (speedup 1.0000x reference)
#include <cuda_runtime.h>
#include <cuda_fp16.h>
#include <math.h>
#include <stdint.h>

// Problem constants (fixed by the dataset)
#define NN 50000
#define EE 400000
#define FF 128
#define HH 8
#define DD 16
#define LL 2

// ---------------- scratch (device globals; no cudaMalloc allowed) ----------
__device__ float g_h[NN * FF];            // node features [N,128]
__device__ float g_kqv[NN * 3 * FF];      // [N,384]: k|q|v
// fp16 kv_rel, lane-interleaved: [etype][node][lane(32) x {k0..k3,v0..v3}] halves
__device__ __half g_kvrel[2 * NN * 256];
__device__ float g_agg[NN * FF];          // aggregated messages (gelu applied)
__device__ int g_cnt[NN];                 // degree histogram / scatter cursor
__device__ int g_rowptr[NN + 1];
__device__ int g_csr[2 * EE];             // packed: src | (etype<<24)

// ================= GEMM: C[M,Nc] = A[M,K] @ B[K,Nc] (+bias, optional skip) ==
// 128x128 tile, BK=16, 256 threads, 8x8 micro-tile, double-buffered smem,
// packed f32x2 FMA (FFMA2).
#define ASTR 132

template <int EPI>
__global__ __launch_bounds__(256, 2)
void gemm128_kernel(const float* __restrict__ A,
                    const float* __restrict__ B,
                    const float* __restrict__ bias,
                    float* __restrict__ C,
                    int M, int Nc, int K,
                    float* __restrict__ hio,
                    const float* __restrict__ skip_p) {
    __shared__ float As[2][16][ASTR];   // [buf][k][row]
    __shared__ float Bs[2][16][128];    // [buf][k][col]

    const int tid = threadIdx.x;
    const int lane = tid & 31;
    const int warp = tid >> 5;
    const int lr = lane >> 3;
    const int lc = lane & 7;
    const int wr = warp >> 1;
    const int wc = warp & 1;
    const int rowOff = wr * 32 + lr * 8;
    const int colOff = wc * 64 + lc * 8;

    const int rowBase = blockIdx.x * 128;
    const int colBase = blockIdx.y * 128;

    const int arow  = tid >> 2;
    const int aquad = tid & 3;
    const int brow = tid >> 5;
    const int bcol = (tid & 31) * 4;

    const int ntiles = K >> 4;

    {
        const int gr0 = rowBase + arow;
        const int gr1 = gr0 + 64;
        float4 a0 = make_float4(0.f, 0.f, 0.f, 0.f), a1 = a0;
        if (gr0 < M) a0 = *(const float4*)(A + (size_t)gr0 * K + aquad * 4);
        if (gr1 < M) a1 = *(const float4*)(A + (size_t)gr1 * K + aquad * 4);
        As[0][aquad * 4 + 0][arow] = a0.x;  As[0][aquad * 4 + 1][arow] = a0.y;
        As[0][aquad * 4 + 2][arow] = a0.z;  As[0][aquad * 4 + 3][arow] = a0.w;
        As[0][aquad * 4 + 0][arow + 64] = a1.x;  As[0][aquad * 4 + 1][arow + 64] = a1.y;
        As[0][aquad * 4 + 2][arow + 64] = a1.z;  As[0][aquad * 4 + 3][arow + 64] = a1.w;
        float4 b0 = *(const float4*)(B + (size_t)brow * Nc + colBase + bcol);
        float4 b1 = *(const float4*)(B + (size_t)(brow + 8) * Nc + colBase + bcol);
        *(float4*)&Bs[0][brow][bcol]     = b0;
        *(float4*)&Bs[0][brow + 8][bcol] = b1;
    }
    __syncthreads();

    unsigned long long acc[8][4];
#pragma unroll
    for (int i = 0; i < 8; i++)
#pragma unroll
        for (int j = 0; j < 4; j++) acc[i][j] = 0ULL;

    for (int kt = 0; kt < ntiles; kt++) {
        const int cur = kt & 1;
        const bool has = (kt + 1 < ntiles);
        float4 pa0, pa1, pb0, pb1;
        if (has) {
            const int k0 = (kt + 1) << 4;
            const int gr0 = rowBase + arow;
            const int gr1 = gr0 + 64;
            pa0 = make_float4(0.f, 0.f, 0.f, 0.f);
            pa1 = pa0;
            if (gr0 < M) pa0 = *(const float4*)(A + (size_t)gr0 * K + k0 + aquad * 4);
            if (gr1 < M) pa1 = *(const float4*)(A + (size_t)gr1 * K + k0 + aquad * 4);
            pb0 = *(const float4*)(B + (size_t)(k0 + brow) * Nc + colBase + bcol);
            pb1 = *(const float4*)(B + (size_t)(k0 + brow + 8) * Nc + colBase + bcol);
        }

#pragma unroll
        for (int kk = 0; kk < 16; kk++) {
            float4 av0 = *(const float4*)&As[cur][kk][rowOff];
            float4 av1 = *(const float4*)&As[cur][kk][rowOff + 4];
            ulonglong2 bv0 = *(const ulonglong2*)&Bs[cur][kk][colOff];
            ulonglong2 bv1 = *(const ulonglong2*)&Bs[cur][kk][colOff + 4];
            unsigned long long b2[4] = {bv0.x, bv0.y, bv1.x, bv1.y};
            float af[8] = {av0.x, av0.y, av0.z, av0.w, av1.x, av1.y, av1.z, av1.w};
#pragma unroll
            for (int i = 0; i < 8; i++) {
                unsigned long long a2;
                asm("mov.b64 %0, {%1, %1};" : "=l"(a2) : "f"(af[i]));
#pragma unroll
                for (int jp = 0; jp < 4; jp++) {
                    asm("fma.rn.f32x2 %0, %1, %2, %0;"
                        : "+l"(acc[i][jp]) : "l"(a2), "l"(b2[jp]));
                }
            }
        }

        if (has) {
            const int nxt = cur ^ 1;
            As[nxt][aquad * 4 + 0][arow] = pa0.x;  As[nxt][aquad * 4 + 1][arow] = pa0.y;
            As[nxt][aquad * 4 + 2][arow] = pa0.z;  As[nxt][aquad * 4 + 3][arow] = pa0.w;
            As[nxt][aquad * 4 + 0][arow + 64] = pa1.x;  As[nxt][aquad * 4 + 1][arow + 64] = pa1.y;
            As[nxt][aquad * 4 + 2][arow + 64] = pa1.z;  As[nxt][aquad * 4 + 3][arow + 64] = pa1.w;
            *(float4*)&Bs[nxt][brow][bcol]     = pb0;
            *(float4*)&Bs[nxt][brow + 8][bcol] = pb1;
            __syncthreads();
        }
    }

    float g = 0.0f;
    if (EPI == 1) g = 1.0f / (1.0f + expf(-skip_p[0]));

    float4 bb0 = *(const float4*)(bias + colBase + colOff);
    float4 bb1 = *(const float4*)(bias + colBase + colOff + 4);

#pragma unroll
    for (int i = 0; i < 8; i++) {
        const int row = rowBase + rowOff + i;
        if (row >= M) continue;
        float c[8];
#pragma unroll
        for (int jp = 0; jp < 4; jp++) {
            asm("mov.b64 {%0, %1}, %2;"
                : "=f"(c[jp * 2]), "=f"(c[jp * 2 + 1]) : "l"(acc[i][jp]));
        }
        c[0] += bb0.x; c[1] += bb0.y; c[2] += bb0.z; c[3] += bb0.w;
        c[4] += bb1.x; c[5] += bb1.y; c[6] += bb1.z; c[7] += bb1.w;
        const size_t o = (size_t)row * Nc + colBase + colOff;
        if (EPI == 0) {
            *(float4*)(C + o)     = make_float4(c[0], c[1], c[2], c[3]);
            *(float4*)(C + o + 4) = make_float4(c[4], c[5], c[6], c[7]);
        } else {
            float4 h0 = *(const float4*)(hio + o);
            float4 h1 = *(const float4*)(hio + o + 4);
            float4 r0, r1;
            r0.x = fmaxf(g * c[0] + (1.0f - g) * h0.x, 0.0f);
            r0.y = fmaxf(g * c[1] + (1.0f - g) * h0.y, 0.0f);
            r0.z = fmaxf(g * c[2] + (1.0f - g) * h0.z, 0.0f);
            r0.w = fmaxf(g * c[3] + (1.0f - g) * h0.w, 0.0f);
            r1.x = fmaxf(g * c[4] + (1.0f - g) * h1.x, 0.0f);
            r1.y = fmaxf(g * c[5] + (1.0f - g) * h1.y, 0.0f);
            r1.z = fmaxf(g * c[6] + (1.0f - g) * h1.z, 0.0f);
            r1.w = fmaxf(g * c[7] + (1.0f - g) * h1.w, 0.0f);
            *(float4*)(hio + o)     = r0;
            *(float4*)(hio + o + 4) = r1;
        }
    }
}

// ---------------- relation transform v2 (fp16 lane-interleaved output) ------
__global__ __launch_bounds__(128)
void rel_kernel(const float* __restrict__ kqv,
                const float* __restrict__ krel_w_l,   // [2,8,16,16]
                const float* __restrict__ vrel_w_l,
                __half* __restrict__ kvrel,           // [2][N][256]
                int Ntot) {
    __shared__ float wk[4096];
    __shared__ float wv[4096];
    __shared__ float sk[8][128];
    __shared__ float sv[8][128];
    __shared__ __half outb[2][8][256];
    const int tid = threadIdx.x;  // 128
    for (int i = tid; i < 4096; i += 128) {
        wk[i] = krel_w_l[i];
        wv[i] = vrel_w_l[i];
    }
    const int h = tid >> 4;
    const int f = tid & 15;
    const int slot = (h * 4 + (f >> 2)) * 8 + (f & 3);
    const int rgrp = tid >> 5;
    const int lane32 = tid & 31;
    const int nchunks = (Ntot + 7) / 8;
    __syncthreads();

    for (int ch = blockIdx.x; ch < nchunks; ch += gridDim.x) {
        const int base = ch * 8;
#pragma unroll
        for (int i2 = 0; i2 < 2; i2++) {
            const int nn = i2 * 4 + rgrp;
            const int n = base + nn;
            float4 k4 = make_float4(0.f, 0.f, 0.f, 0.f), v4 = k4;
            if (n < Ntot) {
                k4 = *(const float4*)(kqv + (size_t)n * 384 + lane32 * 4);
                v4 = *(const float4*)(kqv + (size_t)n * 384 + 256 + lane32 * 4);
            }
            *(float4*)&sk[nn][lane32 * 4] = k4;
            *(float4*)&sv[nn][lane32 * 4] = v4;
        }
        __syncthreads();

#pragma unroll
        for (int nn = 0; nn < 8; nn++) {
            float a0 = 0.f, a1 = 0.f, b0 = 0.f, b1 = 0.f;
#pragma unroll
            for (int d = 0; d < 16; d++) {
                const float kk = sk[nn][h * 16 + d];
                const float vv = sv[nn][h * 16 + d];
                a0 = fmaf(kk, wk[h * 256 + d * 16 + f], a0);
                a1 = fmaf(kk, wk[2048 + h * 256 + d * 16 + f], a1);
                b0 = fmaf(vv, wv[h * 256 + d * 16 + f], b0);
                b1 = fmaf(vv, wv[2048 + h * 256 + d * 16 + f], b1);
            }
            outb[0][nn][slot]     = __float2half(a0);
            outb[0][nn][slot + 4] = __float2half(b0);
            outb[1][nn][slot]     = __float2half(a1);
            outb[1][nn][slot + 4] = __float2half(b1);
        }
        __syncthreads();

#pragma unroll
        for (int it = 0; it < 4; it++) {
            const int idx = it * 128 + tid;
            const int et = idx >> 8;
            const int rem = idx & 255;
            const int nn = rem >> 5;
            const int w = rem & 31;
            const int n = base + nn;
            if (n < Ntot)
                *(uint4*)(kvrel + ((size_t)et * Ntot + n) * 256 + w * 8) =
                    *(const uint4*)&outb[et][nn][w * 8];
        }
        __syncthreads();
    }
}

// ================= CSR build (once per launch; edges static) ================
__global__ void zero_cnt_kernel(int* __restrict__ cnt, int n) {
    int t = blockIdx.x * blockDim.x + threadIdx.x;
    if (t < n) cnt[t] = 0;
}

__global__ void hist_kernel(const int* __restrict__ ef, const int* __restrict__ er,
                            int Ef, int Er, int* __restrict__ cnt) {
    int t = blockIdx.x * blockDim.x + threadIdx.x;
    if (t >= Ef + Er) return;
    int dst = (t < Ef) ? ef[Ef + t] : er[Er + (t - Ef)];
    atomicAdd(cnt + dst, 1);
}

__global__ void scan_kernel(const int* __restrict__ cnt, int* __restrict__ rowptr,
                            int* __restrict__ cur, int n) {
    __shared__ int sums[1024];
    const int tid = threadIdx.x;
    const int chunk = (n + 1023) / 1024;
    const int beg = tid * chunk;
    const int end = min(beg + chunk, n);

    int s = 0;
    for (int i = beg; i < end; i++) s += cnt[i];
    sums[tid] = s;
    __syncthreads();
#pragma unroll
    for (int off = 1; off < 1024; off <<= 1) {
        int v = (tid >= off) ? sums[tid - off] : 0;
        __syncthreads();
        sums[tid] += v;
        __syncthreads();
    }
    int running = sums[tid] - s;
    for (int i = beg; i < end; i++) {
        rowptr[i] = running;
        cur[i] = running;
        running += cnt[i];
    }
    if (tid == 1023) rowptr[n] = sums[1023];
}

__global__ void scatter_kernel(const int* __restrict__ ef, const int* __restrict__ er,
                               int Ef, int Er, int* __restrict__ cur,
                               int* __restrict__ csr) {
    int t = blockIdx.x * blockDim.x + threadIdx.x;
    if (t >= Ef + Er) return;
    int src, dst, et;
    if (t < Ef) { et = 0; src = ef[t]; dst = ef[Ef + t]; }
    else        { int e2 = t - Ef; et = 1; src = er[e2]; dst = er[Er + e2]; }
    int pos = atomicAdd(cur + dst, 1);
    csr[pos] = src | (et << 24);
}

// ========== node attention: warp/node, software-pipelined online softmax ====
// lane = h*4 + part; one uint4 (16B) load per edge per lane: {k half4, v half4}
// Groups of 4 edges; next group's csr+gather loads issue before current math.
__global__ __launch_bounds__(256)
void node_attn_kernel(const int* __restrict__ rowptr, const int* __restrict__ csr,
                      const float* __restrict__ kqv,
                      const __half* __restrict__ kvrel,  // [2][N][256]
                      const float* __restrict__ p_rel_l, // [2,8]
                      float* __restrict__ agg, int Ntot) {
    const int node = blockIdx.x * 8 + (threadIdx.x >> 5);
    if (node >= Ntot) return;
    const int lane = threadIdx.x & 31;
    const int h = lane >> 2;
    const int part = lane & 3;
    const int off = h * 16 + part * 4;
    const int hoff = lane * 8;

    const float4 q = *(const float4*)(kqv + (size_t)node * 384 + 128 + off);
    const float p0 = p_rel_l[h] * 0.25f;
    const float p1 = p_rel_l[8 + h] * 0.25f;

    float m = -INFINITY;
    float den = 0.0f;
    float4 acc = make_float4(0.f, 0.f, 0.f, 0.f);

    const int beg = rowptr[node];
    const int end = rowptr[node + 1];

    if (beg < end) {
        uint4 cc[4];
        float pr[4];   // p factor, or -0.0f marker folded via pad below
        float pad[4];  // 0 for valid edge, -inf for padding

        // group loader: clamped indices, padded logits get -inf
        auto load_group = [&](int i, uint4* c, float* p, float* pd) {
#pragma unroll
            for (int u = 0; u < 4; u++) {
                const int j = i + u;
                const int jj = (j < end) ? j : (end - 1);
                const int pk = __ldg(csr + jj);
                const int src = pk & 0x00FFFFFF;
                const int et = pk >> 24;
                c[u] = *(const uint4*)(kvrel + ((size_t)et * Ntot + src) * 256 + hoff);
                p[u] = et ? p1 : p0;
                pd[u] = (j < end) ? 0.0f : -INFINITY;
            }
        };

        int i = beg;
        load_group(i, cc, pr, pad);

        while (true) {
            const int ni = i + 4;
            const bool more = (ni < end);
            uint4 nc[4];
            float np[4], npad[4];
            if (more) load_group(ni, nc, np, npad);

            // ---- math on current group ----
            float a[4];
            float2 va[4], vb[4];
#pragma unroll
            for (int u = 0; u < 4; u++) {
                const float2 ka = __half22float2(*(const __half2*)&cc[u].x);
                const float2 kb = __half22float2(*(const __half2*)&cc[u].y);
                va[u] = __half22float2(*(const __half2*)&cc[u].z);
                vb[u] = __half22float2(*(const __half2*)&cc[u].w);
                float d = q.x * ka.x + q.y * ka.y + q.z * kb.x + q.w * kb.y;
                d += __shfl_xor_sync(0xFFFFFFFFu, d, 1);
                d += __shfl_xor_sync(0xFFFFFFFFu, d, 2);
                a[u] = d * pr[u] + pad[u];
            }
            const float mx = fmaxf(fmaxf(a[0], a[1]), fmaxf(a[2], a[3]));
            const float mn = fmaxf(m, mx);
            const float sc = __expf(m - mn);
            const float e0 = __expf(a[0] - mn);
            const float e1 = __expf(a[1] - mn);
            const float e2 = __expf(a[2] - mn);
            const float e3 = __expf(a[3] - mn);
            den = den * sc + (e0 + e1) + (e2 + e3);
            acc.x = acc.x * sc + e0 * va[0].x + e1 * va[1].x + e2 * va[2].x + e3 * va[3].x;
            acc.y = acc.y * sc + e0 * va[0].y + e1 * va[1].y + e2 * va[2].y + e3 * va[3].y;
            acc.z = acc.z * sc + e0 * vb[0].x + e1 * vb[1].x + e2 * vb[2].x + e3 * vb[3].x;
            acc.w = acc.w * sc + e0 * vb[0].y + e1 * vb[1].y + e2 * vb[2].y + e3 * vb[3].y;
            m = mn;

            if (!more) break;
#pragma unroll
            for (int u = 0; u < 4; u++) {
                cc[u] = nc[u];
                pr[u] = np[u];
                pad[u] = npad[u];
            }
            i = ni;
        }
    }

    const float inv = 1.0f / (den + 1e-16f);
    float4 r;
    const float c = 0.70710678118654752440f;
    float v0 = acc.x * inv, v1 = acc.y * inv, v2 = acc.z * inv, v3 = acc.w * inv;
    r.x = 0.5f * v0 * (1.0f + erff(v0 * c));
    r.y = 0.5f * v1 * (1.0f + erff(v1 * c));
    r.z = 0.5f * v2 * (1.0f + erff(v2 * c));
    r.w = 0.5f * v3 * (1.0f + erff(v3 * c));
    *(float4*)(agg + (size_t)node * 128 + off) = r;
}

// ---------------- head: logits [N,2] -----------------------------------------
__global__ void head_kernel(const float* __restrict__ h, const float* __restrict__ w,
                            const float* __restrict__ b, float* __restrict__ out, int n) {
    int gw = (blockIdx.x * blockDim.x + threadIdx.x) >> 5;
    int lane = threadIdx.x & 31;
    if (gw >= n) return;
    const float* hr = h + (size_t)gw * 128;
    float s0 = 0.f, s1 = 0.f;
#pragma unroll
    for (int k = lane; k < 128; k += 32) {
        float hv = hr[k];
        s0 = fmaf(hv, w[k * 2 + 0], s0);
        s1 = fmaf(hv, w[k * 2 + 1], s1);
    }
#pragma unroll
    for (int o = 16; o > 0; o >>= 1) {
        s0 += __shfl_down_sync(0xFFFFFFFFu, s0, o);
        s1 += __shfl_down_sync(0xFFFFFFFFu, s1, o);
    }
    if (lane == 0) {
        out[(size_t)gw * 2 + 0] = s0 + b[0];
        out[(size_t)gw * 2 + 1] = s1 + b[1];
    }
}

// ---------------- launch ------------------------------------------------------
extern "C" void kernel_launch(void* const* d_in, const int* in_sizes, int n_in,
                              void* d_out, int out_size) {
    const float* x       = (const float*)d_in[0];
    const int*   ef      = (const int*)d_in[1];
    const int*   er      = (const int*)d_in[2];
    const float* in_w    = (const float*)d_in[3];
    const float* in_b    = (const float*)d_in[4];
    const float* kqv_w   = (const float*)d_in[5];
    const float* kqv_b   = (const float*)d_in[6];
    const float* krel_w  = (const float*)d_in[7];
    const float* vrel_w  = (const float*)d_in[8];
    const float* p_rel   = (const float*)d_in[9];
    const float* out_w   = (const float*)d_in[10];
    const float* out_b   = (const float*)d_in[11];
    const float* skip    = (const float*)d_in[12];
    const float* head_w  = (const float*)d_in[13];
    const float* head_b  = (const float*)d_in[14];
    float* out = (float*)d_out;

    const int N  = in_sizes[0] / FF;
    const int Ef = in_sizes[1] / 2;
    const int Er = in_sizes[2] / 2;
    const int Etot = Ef + Er;

    float* hbuf;   cudaGetSymbolAddress((void**)&hbuf, g_h);
    float* kqv;    cudaGetSymbolAddress((void**)&kqv, g_kqv);
    __half* kvrel; cudaGetSymbolAddress((void**)&kvrel, g_kvrel);
    float* agg;    cudaGetSymbolAddress((void**)&agg, g_agg);
    int* cnt;      cudaGetSymbolAddress((void**)&cnt, g_cnt);
    int* rowptr;   cudaGetSymbolAddress((void**)&rowptr, g_rowptr);
    int* csr;      cudaGetSymbolAddress((void**)&csr, g_csr);

    const int gmRows = (N + 127) / 128;
    const int relBlocks = 640;

    zero_cnt_kernel<<<(N + 255) / 256, 256>>>(cnt, N);
    gemm128_kernel<0><<<dim3(gmRows, FF / 128), 256>>>(x, in_w, in_b, hbuf,
                                                       N, FF, FF, nullptr, nullptr);
    hist_kernel<<<(Etot + 255) / 256, 256>>>(ef, er, Ef, Er, cnt);
    gemm128_kernel<0><<<dim3(gmRows, (3 * FF) / 128), 256>>>(
        hbuf, kqv_w, kqv_b, kqv, N, 3 * FF, FF, nullptr, nullptr);
    scan_kernel<<<1, 1024>>>(cnt, rowptr, cnt, N);
    rel_kernel<<<relBlocks, 128>>>(kqv, krel_w, vrel_w, kvrel, N);
    scatter_kernel<<<(Etot + 255) / 256, 256>>>(ef, er, Ef, Er, cnt, csr);

    for (int l = 0; l < LL; l++) {
        if (l > 0) {
            gemm128_kernel<0><<<dim3(gmRows, (3 * FF) / 128), 256>>>(
                hbuf, kqv_w + (size_t)l * FF * 3 * FF, kqv_b + (size_t)l * 3 * FF,
                kqv, N, 3 * FF, FF, nullptr, nullptr);
            rel_kernel<<<relBlocks, 128>>>(kqv,
                                           krel_w + (size_t)l * 2 * HH * DD * DD,
                                           vrel_w + (size_t)l * 2 * HH * DD * DD,
                                           kvrel, N);
        }

        node_attn_kernel<<<(N + 7) / 8, 256>>>(rowptr, csr, kqv, kvrel,
                                               p_rel + (size_t)l * 2 * HH, agg, N);

        gemm128_kernel<1><<<dim3(gmRows, FF / 128), 256>>>(
            agg, out_w + (size_t)l * FF * FF, out_b + (size_t)l * FF,
            nullptr, N, FF, FF, hbuf, skip + l);
    }

    head_kernel<<<(N * 32 + 255) / 256, 256>>>(hbuf, head_w, head_b, out, N);
}

// round 11
// speedup vs baseline: 1.1929x; 1.1929x over previous
#include <cuda_runtime.h>
#include <cuda_fp16.h>
#include <math.h>
#include <stdint.h>

// Problem constants (fixed by the dataset)
#define NN 50000
#define EE 400000
#define FF 128
#define HH 8
#define DD 16
#define LL 2

// ---------------- scratch (device globals; no cudaMalloc allowed) ----------
__device__ float g_h[NN * FF];            // node features [N,128]
__device__ float g_kqv[NN * 3 * FF];      // [N,384]: k|q|v
// fp16 kv_rel, lane-interleaved: [etype][node][lane(32) x {k0..k3,v0..v3}] halves
__device__ __half g_kvrel[2 * NN * 256];
__device__ float g_agg[NN * FF];          // aggregated messages (gelu applied)
__device__ int g_cnt[NN];                 // degree histogram / scatter cursor
__device__ int g_rowptr[NN + 1];
__device__ int g_csr[2 * EE];             // packed: src | (etype<<24)

// ================= GEMM: C[M,Nc] = A[M,K] @ B[K,Nc] (+bias, optional skip) ==
// 128x128 tile, BK=16, 256 threads, 8x8 micro-tile, double-buffered smem,
// packed f32x2 FMA (FFMA2).
#define ASTR 132

template <int EPI>
__global__ __launch_bounds__(256, 2)
void gemm128_kernel(const float* __restrict__ A,
                    const float* __restrict__ B,
                    const float* __restrict__ bias,
                    float* __restrict__ C,
                    int M, int Nc, int K,
                    float* __restrict__ hio,
                    const float* __restrict__ skip_p) {
    __shared__ float As[2][16][ASTR];   // [buf][k][row]
    __shared__ float Bs[2][16][128];    // [buf][k][col]

    const int tid = threadIdx.x;
    const int lane = tid & 31;
    const int warp = tid >> 5;
    const int lr = lane >> 3;
    const int lc = lane & 7;
    const int wr = warp >> 1;
    const int wc = warp & 1;
    const int rowOff = wr * 32 + lr * 8;
    const int colOff = wc * 64 + lc * 8;

    const int rowBase = blockIdx.x * 128;
    const int colBase = blockIdx.y * 128;

    const int arow  = tid >> 2;
    const int aquad = tid & 3;
    const int brow = tid >> 5;
    const int bcol = (tid & 31) * 4;

    const int ntiles = K >> 4;

    {
        const int gr0 = rowBase + arow;
        const int gr1 = gr0 + 64;
        float4 a0 = make_float4(0.f, 0.f, 0.f, 0.f), a1 = a0;
        if (gr0 < M) a0 = *(const float4*)(A + (size_t)gr0 * K + aquad * 4);
        if (gr1 < M) a1 = *(const float4*)(A + (size_t)gr1 * K + aquad * 4);
        As[0][aquad * 4 + 0][arow] = a0.x;  As[0][aquad * 4 + 1][arow] = a0.y;
        As[0][aquad * 4 + 2][arow] = a0.z;  As[0][aquad * 4 + 3][arow] = a0.w;
        As[0][aquad * 4 + 0][arow + 64] = a1.x;  As[0][aquad * 4 + 1][arow + 64] = a1.y;
        As[0][aquad * 4 + 2][arow + 64] = a1.z;  As[0][aquad * 4 + 3][arow + 64] = a1.w;
        float4 b0 = *(const float4*)(B + (size_t)brow * Nc + colBase + bcol);
        float4 b1 = *(const float4*)(B + (size_t)(brow + 8) * Nc + colBase + bcol);
        *(float4*)&Bs[0][brow][bcol]     = b0;
        *(float4*)&Bs[0][brow + 8][bcol] = b1;
    }
    __syncthreads();

    unsigned long long acc[8][4];
#pragma unroll
    for (int i = 0; i < 8; i++)
#pragma unroll
        for (int j = 0; j < 4; j++) acc[i][j] = 0ULL;

    for (int kt = 0; kt < ntiles; kt++) {
        const int cur = kt & 1;
        const bool has = (kt + 1 < ntiles);
        float4 pa0, pa1, pb0, pb1;
        if (has) {
            const int k0 = (kt + 1) << 4;
            const int gr0 = rowBase + arow;
            const int gr1 = gr0 + 64;
            pa0 = make_float4(0.f, 0.f, 0.f, 0.f);
            pa1 = pa0;
            if (gr0 < M) pa0 = *(const float4*)(A + (size_t)gr0 * K + k0 + aquad * 4);
            if (gr1 < M) pa1 = *(const float4*)(A + (size_t)gr1 * K + k0 + aquad * 4);
            pb0 = *(const float4*)(B + (size_t)(k0 + brow) * Nc + colBase + bcol);
            pb1 = *(const float4*)(B + (size_t)(k0 + brow + 8) * Nc + colBase + bcol);
        }

#pragma unroll
        for (int kk = 0; kk < 16; kk++) {
            float4 av0 = *(const float4*)&As[cur][kk][rowOff];
            float4 av1 = *(const float4*)&As[cur][kk][rowOff + 4];
            ulonglong2 bv0 = *(const ulonglong2*)&Bs[cur][kk][colOff];
            ulonglong2 bv1 = *(const ulonglong2*)&Bs[cur][kk][colOff + 4];
            unsigned long long b2[4] = {bv0.x, bv0.y, bv1.x, bv1.y};
            float af[8] = {av0.x, av0.y, av0.z, av0.w, av1.x, av1.y, av1.z, av1.w};
#pragma unroll
            for (int i = 0; i < 8; i++) {
                unsigned long long a2;
                asm("mov.b64 %0, {%1, %1};" : "=l"(a2) : "f"(af[i]));
#pragma unroll
                for (int jp = 0; jp < 4; jp++) {
                    asm("fma.rn.f32x2 %0, %1, %2, %0;"
                        : "+l"(acc[i][jp]) : "l"(a2), "l"(b2[jp]));
                }
            }
        }

        if (has) {
            const int nxt = cur ^ 1;
            As[nxt][aquad * 4 + 0][arow] = pa0.x;  As[nxt][aquad * 4 + 1][arow] = pa0.y;
            As[nxt][aquad * 4 + 2][arow] = pa0.z;  As[nxt][aquad * 4 + 3][arow] = pa0.w;
            As[nxt][aquad * 4 + 0][arow + 64] = pa1.x;  As[nxt][aquad * 4 + 1][arow + 64] = pa1.y;
            As[nxt][aquad * 4 + 2][arow + 64] = pa1.z;  As[nxt][aquad * 4 + 3][arow + 64] = pa1.w;
            *(float4*)&Bs[nxt][brow][bcol]     = pb0;
            *(float4*)&Bs[nxt][brow + 8][bcol] = pb1;
            __syncthreads();
        }
    }

    float g = 0.0f;
    if (EPI == 1) g = 1.0f / (1.0f + expf(-skip_p[0]));

    float4 bb0 = *(const float4*)(bias + colBase + colOff);
    float4 bb1 = *(const float4*)(bias + colBase + colOff + 4);

#pragma unroll
    for (int i = 0; i < 8; i++) {
        const int row = rowBase + rowOff + i;
        if (row >= M) continue;
        float c[8];
#pragma unroll
        for (int jp = 0; jp < 4; jp++) {
            asm("mov.b64 {%0, %1}, %2;"
                : "=f"(c[jp * 2]), "=f"(c[jp * 2 + 1]) : "l"(acc[i][jp]));
        }
        c[0] += bb0.x; c[1] += bb0.y; c[2] += bb0.z; c[3] += bb0.w;
        c[4] += bb1.x; c[5] += bb1.y; c[6] += bb1.z; c[7] += bb1.w;
        const size_t o = (size_t)row * Nc + colBase + colOff;
        if (EPI == 0) {
            *(float4*)(C + o)     = make_float4(c[0], c[1], c[2], c[3]);
            *(float4*)(C + o + 4) = make_float4(c[4], c[5], c[6], c[7]);
        } else {
            float4 h0 = *(const float4*)(hio + o);
            float4 h1 = *(const float4*)(hio + o + 4);
            float4 r0, r1;
            r0.x = fmaxf(g * c[0] + (1.0f - g) * h0.x, 0.0f);
            r0.y = fmaxf(g * c[1] + (1.0f - g) * h0.y, 0.0f);
            r0.z = fmaxf(g * c[2] + (1.0f - g) * h0.z, 0.0f);
            r0.w = fmaxf(g * c[3] + (1.0f - g) * h0.w, 0.0f);
            r1.x = fmaxf(g * c[4] + (1.0f - g) * h1.x, 0.0f);
            r1.y = fmaxf(g * c[5] + (1.0f - g) * h1.y, 0.0f);
            r1.z = fmaxf(g * c[6] + (1.0f - g) * h1.z, 0.0f);
            r1.w = fmaxf(g * c[7] + (1.0f - g) * h1.w, 0.0f);
            *(float4*)(hio + o)     = r0;
            *(float4*)(hio + o + 4) = r1;
        }
    }
}

// ---------------- relation transform v2 (fp16 lane-interleaved output) ------
__global__ __launch_bounds__(128)
void rel_kernel(const float* __restrict__ kqv,
                const float* __restrict__ krel_w_l,   // [2,8,16,16]
                const float* __restrict__ vrel_w_l,
                __half* __restrict__ kvrel,           // [2][N][256]
                int Ntot) {
    __shared__ float wk[4096];
    __shared__ float wv[4096];
    __shared__ float sk[8][128];
    __shared__ float sv[8][128];
    __shared__ __half outb[2][8][256];
    const int tid = threadIdx.x;  // 128
    for (int i = tid; i < 4096; i += 128) {
        wk[i] = krel_w_l[i];
        wv[i] = vrel_w_l[i];
    }
    const int h = tid >> 4;
    const int f = tid & 15;
    const int slot = (h * 4 + (f >> 2)) * 8 + (f & 3);
    const int rgrp = tid >> 5;
    const int lane32 = tid & 31;
    const int nchunks = (Ntot + 7) / 8;
    __syncthreads();

    for (int ch = blockIdx.x; ch < nchunks; ch += gridDim.x) {
        const int base = ch * 8;
#pragma unroll
        for (int i2 = 0; i2 < 2; i2++) {
            const int nn = i2 * 4 + rgrp;
            const int n = base + nn;
            float4 k4 = make_float4(0.f, 0.f, 0.f, 0.f), v4 = k4;
            if (n < Ntot) {
                k4 = *(const float4*)(kqv + (size_t)n * 384 + lane32 * 4);
                v4 = *(const float4*)(kqv + (size_t)n * 384 + 256 + lane32 * 4);
            }
            *(float4*)&sk[nn][lane32 * 4] = k4;
            *(float4*)&sv[nn][lane32 * 4] = v4;
        }
        __syncthreads();

#pragma unroll
        for (int nn = 0; nn < 8; nn++) {
            float a0 = 0.f, a1 = 0.f, b0 = 0.f, b1 = 0.f;
#pragma unroll
            for (int d = 0; d < 16; d++) {
                const float kk = sk[nn][h * 16 + d];
                const float vv = sv[nn][h * 16 + d];
                a0 = fmaf(kk, wk[h * 256 + d * 16 + f], a0);
                a1 = fmaf(kk, wk[2048 + h * 256 + d * 16 + f], a1);
                b0 = fmaf(vv, wv[h * 256 + d * 16 + f], b0);
                b1 = fmaf(vv, wv[2048 + h * 256 + d * 16 + f], b1);
            }
            outb[0][nn][slot]     = __float2half(a0);
            outb[0][nn][slot + 4] = __float2half(b0);
            outb[1][nn][slot]     = __float2half(a1);
            outb[1][nn][slot + 4] = __float2half(b1);
        }
        __syncthreads();

#pragma unroll
        for (int it = 0; it < 4; it++) {
            const int idx = it * 128 + tid;
            const int et = idx >> 8;
            const int rem = idx & 255;
            const int nn = rem >> 5;
            const int w = rem & 31;
            const int n = base + nn;
            if (n < Ntot)
                *(uint4*)(kvrel + ((size_t)et * Ntot + n) * 256 + w * 8) =
                    *(const uint4*)&outb[et][nn][w * 8];
        }
        __syncthreads();
    }
}

// ================= CSR build (once per launch; edges static) ================
__global__ void hist_kernel(const int* __restrict__ ef, const int* __restrict__ er,
                            int Ef, int Er, int* __restrict__ cnt) {
    int t = blockIdx.x * blockDim.x + threadIdx.x;
    if (t >= Ef + Er) return;
    int dst = (t < Ef) ? ef[Ef + t] : er[Er + (t - Ef)];
    atomicAdd(cnt + dst, 1);
}

__global__ void scan_kernel(const int* __restrict__ cnt, int* __restrict__ rowptr,
                            int* __restrict__ cur, int n) {
    __shared__ int sums[1024];
    const int tid = threadIdx.x;
    const int chunk = (n + 1023) / 1024;
    const int beg = tid * chunk;
    const int end = min(beg + chunk, n);

    int s = 0;
    for (int i = beg; i < end; i++) s += cnt[i];
    sums[tid] = s;
    __syncthreads();
#pragma unroll
    for (int off = 1; off < 1024; off <<= 1) {
        int v = (tid >= off) ? sums[tid - off] : 0;
        __syncthreads();
        sums[tid] += v;
        __syncthreads();
    }
    int running = sums[tid] - s;
    for (int i = beg; i < end; i++) {
        rowptr[i] = running;
        cur[i] = running;
        running += cnt[i];
    }
    if (tid == 1023) rowptr[n] = sums[1023];
}

__global__ void scatter_kernel(const int* __restrict__ ef, const int* __restrict__ er,
                               int Ef, int Er, int* __restrict__ cur,
                               int* __restrict__ csr) {
    int t = blockIdx.x * blockDim.x + threadIdx.x;
    if (t >= Ef + Er) return;
    int src, dst, et;
    if (t < Ef) { et = 0; src = ef[t]; dst = ef[Ef + t]; }
    else        { int e2 = t - Ef; et = 1; src = er[e2]; dst = er[Er + e2]; }
    int pos = atomicAdd(cur + dst, 1);
    csr[pos] = src | (et << 24);
}

// ========== node attention: warp per node, 4-way unrolled online softmax ====
// lane = h*4 + part; one uint4 (16B) load per edge per lane: {k half4, v half4}
__global__ __launch_bounds__(256)
void node_attn_kernel(const int* __restrict__ rowptr, const int* __restrict__ csr,
                      const float* __restrict__ kqv,
                      const __half* __restrict__ kvrel,  // [2][N][256]
                      const float* __restrict__ p_rel_l, // [2,8]
                      float* __restrict__ agg, int Ntot) {
    const int node = blockIdx.x * 8 + (threadIdx.x >> 5);
    if (node >= Ntot) return;
    const int lane = threadIdx.x & 31;
    const int h = lane >> 2;
    const int part = lane & 3;
    const int off = h * 16 + part * 4;
    const int hoff = lane * 8;

    const float4 q = *(const float4*)(kqv + (size_t)node * 384 + 128 + off);
    const float p0 = p_rel_l[h] * 0.25f;
    const float p1 = p_rel_l[8 + h] * 0.25f;

    float m = -INFINITY;
    float den = 0.0f;
    float4 acc = make_float4(0.f, 0.f, 0.f, 0.f);

    const int beg = rowptr[node];
    const int end = rowptr[node + 1];
    int i = beg;

    // 4-way unrolled: 4 independent gathers in flight, one batched merge
    for (; i + 3 < end; i += 4) {
        uint4 cc[4];
        float pr[4];
#pragma unroll
        for (int u = 0; u < 4; u++) {
            const int pk = __ldg(csr + i + u);
            const int src = pk & 0x00FFFFFF;
            const int et = pk >> 24;
            cc[u] = *(const uint4*)(kvrel + ((size_t)et * Ntot + src) * 256 + hoff);
            pr[u] = et ? p1 : p0;
        }
        float a[4];
        float2 va[4], vb[4];
#pragma unroll
        for (int u = 0; u < 4; u++) {
            const float2 ka = __half22float2(*(const __half2*)&cc[u].x);
            const float2 kb = __half22float2(*(const __half2*)&cc[u].y);
            va[u] = __half22float2(*(const __half2*)&cc[u].z);
            vb[u] = __half22float2(*(const __half2*)&cc[u].w);
            float d = q.x * ka.x + q.y * ka.y + q.z * kb.x + q.w * kb.y;
            d += __shfl_xor_sync(0xFFFFFFFFu, d, 1);
            d += __shfl_xor_sync(0xFFFFFFFFu, d, 2);
            a[u] = d * pr[u];
        }
        const float mx = fmaxf(fmaxf(a[0], a[1]), fmaxf(a[2], a[3]));
        const float mn = fmaxf(m, mx);
        const float sc = __expf(m - mn);
        const float e0 = __expf(a[0] - mn);
        const float e1 = __expf(a[1] - mn);
        const float e2 = __expf(a[2] - mn);
        const float e3 = __expf(a[3] - mn);
        den = den * sc + (e0 + e1) + (e2 + e3);
        acc.x = acc.x * sc + e0 * va[0].x + e1 * va[1].x + e2 * va[2].x + e3 * va[3].x;
        acc.y = acc.y * sc + e0 * va[0].y + e1 * va[1].y + e2 * va[2].y + e3 * va[3].y;
        acc.z = acc.z * sc + e0 * vb[0].x + e1 * vb[1].x + e2 * vb[2].x + e3 * vb[3].x;
        acc.w = acc.w * sc + e0 * vb[0].y + e1 * vb[1].y + e2 * vb[2].y + e3 * vb[3].y;
        m = mn;
    }
    for (; i < end; i++) {
        const int pk = __ldg(csr + i);
        const int src = pk & 0x00FFFFFF, et = pk >> 24;
        const uint4 c0 = *(const uint4*)(kvrel + ((size_t)et * Ntot + src) * 256 + hoff);
        const float2 ka = __half22float2(*(const __half2*)&c0.x);
        const float2 kb = __half22float2(*(const __half2*)&c0.y);
        const float2 va1 = __half22float2(*(const __half2*)&c0.z);
        const float2 vb1 = __half22float2(*(const __half2*)&c0.w);
        float d = q.x * ka.x + q.y * ka.y + q.z * kb.x + q.w * kb.y;
        d += __shfl_xor_sync(0xFFFFFFFFu, d, 1);
        d += __shfl_xor_sync(0xFFFFFFFFu, d, 2);
        const float a = d * (et ? p1 : p0);
        const float mn = fmaxf(m, a);
        const float sc = __expf(m - mn);
        const float ex = __expf(a - mn);
        den = den * sc + ex;
        acc.x = acc.x * sc + ex * va1.x;
        acc.y = acc.y * sc + ex * va1.y;
        acc.z = acc.z * sc + ex * vb1.x;
        acc.w = acc.w * sc + ex * vb1.y;
        m = mn;
    }

    const float inv = 1.0f / (den + 1e-16f);
    float4 r;
    const float c = 0.70710678118654752440f;
    float v0 = acc.x * inv, v1 = acc.y * inv, v2 = acc.z * inv, v3 = acc.w * inv;
    r.x = 0.5f * v0 * (1.0f + erff(v0 * c));
    r.y = 0.5f * v1 * (1.0f + erff(v1 * c));
    r.z = 0.5f * v2 * (1.0f + erff(v2 * c));
    r.w = 0.5f * v3 * (1.0f + erff(v3 * c));
    *(float4*)(agg + (size_t)node * 128 + off) = r;
}

// ---------------- head: logits [N,2] -----------------------------------------
__global__ void head_kernel(const float* __restrict__ h, const float* __restrict__ w,
                            const float* __restrict__ b, float* __restrict__ out, int n) {
    int gw = (blockIdx.x * blockDim.x + threadIdx.x) >> 5;
    int lane = threadIdx.x & 31;
    if (gw >= n) return;
    const float* hr = h + (size_t)gw * 128;
    float s0 = 0.f, s1 = 0.f;
#pragma unroll
    for (int k = lane; k < 128; k += 32) {
        float hv = hr[k];
        s0 = fmaf(hv, w[k * 2 + 0], s0);
        s1 = fmaf(hv, w[k * 2 + 1], s1);
    }
#pragma unroll
    for (int o = 16; o > 0; o >>= 1) {
        s0 += __shfl_down_sync(0xFFFFFFFFu, s0, o);
        s1 += __shfl_down_sync(0xFFFFFFFFu, s1, o);
    }
    if (lane == 0) {
        out[(size_t)gw * 2 + 0] = s0 + b[0];
        out[(size_t)gw * 2 + 1] = s1 + b[1];
    }
}

// ---------------- launch ------------------------------------------------------
extern "C" void kernel_launch(void* const* d_in, const int* in_sizes, int n_in,
                              void* d_out, int out_size) {
    const float* x       = (const float*)d_in[0];
    const int*   ef      = (const int*)d_in[1];
    const int*   er      = (const int*)d_in[2];
    const float* in_w    = (const float*)d_in[3];
    const float* in_b    = (const float*)d_in[4];
    const float* kqv_w   = (const float*)d_in[5];
    const float* kqv_b   = (const float*)d_in[6];
    const float* krel_w  = (const float*)d_in[7];
    const float* vrel_w  = (const float*)d_in[8];
    const float* p_rel   = (const float*)d_in[9];
    const float* out_w   = (const float*)d_in[10];
    const float* out_b   = (const float*)d_in[11];
    const float* skip    = (const float*)d_in[12];
    const float* head_w  = (const float*)d_in[13];
    const float* head_b  = (const float*)d_in[14];
    float* out = (float*)d_out;

    const int N  = in_sizes[0] / FF;
    const int Ef = in_sizes[1] / 2;
    const int Er = in_sizes[2] / 2;
    const int Etot = Ef + Er;

    float* hbuf;   cudaGetSymbolAddress((void**)&hbuf, g_h);
    float* kqv;    cudaGetSymbolAddress((void**)&kqv, g_kqv);
    __half* kvrel; cudaGetSymbolAddress((void**)&kvrel, g_kvrel);
    float* agg;    cudaGetSymbolAddress((void**)&agg, g_agg);
    int* cnt;      cudaGetSymbolAddress((void**)&cnt, g_cnt);
    int* rowptr;   cudaGetSymbolAddress((void**)&rowptr, g_rowptr);
    int* csr;      cudaGetSymbolAddress((void**)&csr, g_csr);

    const int gmRows = (N + 127) / 128;
    const int relBlocks = 640;

    // Side stream + fork/join events. Created once on the FIRST call (the
    // correctness run, which is NOT graph-captured), reused identically on
    // every call so the captured graph is the same every time.
    static cudaStream_t s2 = nullptr;
    static cudaEvent_t evFork = nullptr, evJoin = nullptr;
    if (s2 == nullptr) {
        cudaStreamCreateWithFlags(&s2, cudaStreamNonBlocking);
        cudaEventCreateWithFlags(&evFork, cudaEventDisableTiming);
        cudaEventCreateWithFlags(&evJoin, cudaEventDisableTiming);
    }

    // ---- fork: CSR build chain on s2, GEMM/rel chain on main stream ----
    cudaEventRecord(evFork, 0);
    cudaStreamWaitEvent(s2, evFork, 0);

    cudaMemsetAsync(cnt, 0, (size_t)N * sizeof(int), s2);
    hist_kernel<<<(Etot + 255) / 256, 256, 0, s2>>>(ef, er, Ef, Er, cnt);
    scan_kernel<<<1, 1024, 0, s2>>>(cnt, rowptr, cnt, N);
    scatter_kernel<<<(Etot + 255) / 256, 256, 0, s2>>>(ef, er, Ef, Er, cnt, csr);
    cudaEventRecord(evJoin, s2);

    // main stream: h = x @ in_w + in_b ; kqv(l=0) ; rel(l=0)
    gemm128_kernel<0><<<dim3(gmRows, FF / 128), 256>>>(x, in_w, in_b, hbuf,
                                                       N, FF, FF, nullptr, nullptr);
    gemm128_kernel<0><<<dim3(gmRows, (3 * FF) / 128), 256>>>(
        hbuf, kqv_w, kqv_b, kqv, N, 3 * FF, FF, nullptr, nullptr);
    rel_kernel<<<relBlocks, 128>>>(kqv, krel_w, vrel_w, kvrel, N);

    // ---- join: attention needs both chains ----
    cudaStreamWaitEvent(0, evJoin, 0);

    for (int l = 0; l < LL; l++) {
        if (l > 0) {
            gemm128_kernel<0><<<dim3(gmRows, (3 * FF) / 128), 256>>>(
                hbuf, kqv_w + (size_t)l * FF * 3 * FF, kqv_b + (size_t)l * 3 * FF,
                kqv, N, 3 * FF, FF, nullptr, nullptr);
            rel_kernel<<<relBlocks, 128>>>(kqv,
                                           krel_w + (size_t)l * 2 * HH * DD * DD,
                                           vrel_w + (size_t)l * 2 * HH * DD * DD,
                                           kvrel, N);
        }

        node_attn_kernel<<<(N + 7) / 8, 256>>>(rowptr, csr, kqv, kvrel,
                                               p_rel + (size_t)l * 2 * HH, agg, N);

        gemm128_kernel<1><<<dim3(gmRows, FF / 128), 256>>>(
            agg, out_w + (size_t)l * FF * FF, out_b + (size_t)l * FF,
            nullptr, N, FF, FF, hbuf, skip + l);
    }

    head_kernel<<<(N * 32 + 255) / 256, 256>>>(hbuf, head_w, head_b, out, N);
}